// round 10
// baseline (speedup 1.0000x reference)
#include <cuda_runtime.h>
#include <cuda_fp16.h>
#include <math.h>
#include <stdint.h>

#define BB   4
#define SS   2048
#define HH   1024
#define NHH  16
#define HDD  64
#define ROWS (BB*SS)            // 8192
#define TOT  (ROWS*HH)          // 8,388,608
#define LOG2E 1.4426950408889634f

// ---------------- device scratch (no allocs allowed) ----------------
__device__ __half g_Xh[TOT];
__device__ __half g_Wh[4][HH*HH];   // Wq, Wk, Wv, Wd (half)
__device__ __half g_Qh[TOT];
__device__ __half g_Kh[TOT];
__device__ __half g_Vh[TOT];
__device__ __half g_Ch[TOT];
__device__ float  g_Hd[TOT];

// ---------------- PTX helpers ----------------
__device__ __forceinline__ uint32_t smem_u32(const void* p) {
    return (uint32_t)__cvta_generic_to_shared(p);
}
__device__ __forceinline__ uint32_t h2_as_u32(__half2 h) {
    union { __half2 h2; uint32_t u; } cvt;
    cvt.h2 = h;
    return cvt.u;
}
#define CP_ASYNC(dst, src) asm volatile("cp.async.cg.shared.global [%0], [%1], 16;\n" :: "r"(dst), "l"(src))
#define CP_COMMIT()  asm volatile("cp.async.commit_group;\n")
#define CP_WAIT0()   asm volatile("cp.async.wait_group 0;\n")

#define MBARRIER_INIT(addr, cnt) \
    asm volatile("mbarrier.init.shared.b64 [%0], %1;" :: "r"(addr), "r"(cnt) : "memory")
#define MBARRIER_EXPECT_TX(addr, bytes) \
    asm volatile("mbarrier.arrive.expect_tx.shared.b64 _, [%0], %1;" :: "r"(addr), "r"(bytes) : "memory")
// 1D bulk copy global->shared, completion via mbarrier (UBLKCP; no swizzle)
#define BULK_G2S(dst, src, size, mbar) \
    asm volatile("cp.async.bulk.shared::cluster.global.mbarrier::complete_tx::bytes [%0], [%1], %2, [%3];" \
        :: "r"(dst), "l"(src), "r"(size), "r"(mbar) : "memory")

__device__ __forceinline__ void mbar_wait(uint32_t mbar, uint32_t parity) {
    asm volatile(
        "{\n\t.reg .pred P;\n\t"
        "W_%=:\n\t"
        "mbarrier.try_wait.parity.acquire.cta.shared::cta.b64 P, [%0], %1;\n\t"
        "@!P bra W_%=;\n\t}"
        :: "r"(mbar), "r"(parity) : "memory");
}

__device__ __forceinline__ void ldsm4(uint32_t* r, uint32_t addr) {
    asm volatile("ldmatrix.sync.aligned.m8n8.x4.shared.b16 {%0,%1,%2,%3}, [%4];\n"
                 : "=r"(r[0]), "=r"(r[1]), "=r"(r[2]), "=r"(r[3]) : "r"(addr));
}
__device__ __forceinline__ void ldsm4t(uint32_t* r, uint32_t addr) {
    asm volatile("ldmatrix.sync.aligned.m8n8.x4.trans.shared.b16 {%0,%1,%2,%3}, [%4];\n"
                 : "=r"(r[0]), "=r"(r[1]), "=r"(r[2]), "=r"(r[3]) : "r"(addr));
}
__device__ __forceinline__ void mma16816(float* d, const uint32_t* a, const uint32_t* b) {
    asm volatile("mma.sync.aligned.m16n8k16.row.col.f32.f16.f16.f32 "
                 "{%0,%1,%2,%3}, {%4,%5,%6,%7}, {%8,%9}, {%0,%1,%2,%3};\n"
                 : "+f"(d[0]), "+f"(d[1]), "+f"(d[2]), "+f"(d[3])
                 : "r"(a[0]), "r"(a[1]), "r"(a[2]), "r"(a[3]), "r"(b[0]), "r"(b[1]));
}

// ---------------- fp32 -> fp16 conversions ----------------
__global__ void f2h_kernel(const float4* __restrict__ in, __half2* __restrict__ out, int n4) {
    int i = blockIdx.x * blockDim.x + threadIdx.x;
    if (i < n4) {
        float4 v = in[i];
        out[2*i + 0] = __floats2half2_rn(v.x, v.y);
        out[2*i + 1] = __floats2half2_rn(v.z, v.w);
    }
}
__global__ void f2h_w_kernel(const float4* __restrict__ w0, const float4* __restrict__ w1,
                             const float4* __restrict__ w2, const float4* __restrict__ w3,
                             __half2* __restrict__ out) {
    const float4* srcs[4] = { w0, w1, w2, w3 };
    const float4* src = srcs[blockIdx.y];
    __half2* dst = out + (size_t)blockIdx.y * (HH * HH / 2);
    int i = blockIdx.x * blockDim.x + threadIdx.x;
    float4 v = src[i];
    dst[2*i + 0] = __floats2half2_rn(v.x, v.y);
    dst[2*i + 1] = __floats2half2_rn(v.z, v.w);
}

// ---------------------------------------------------------------------------
// Bulk-fed f16 GEMM: C[M,N] = A[M,K] @ B[K,N] + bias.
// Block 128x128, K-tile 32, 8 warps (2x4) of 64x32. 4-stage mbarrier pipeline,
// per-row cp.async.bulk into the PROVEN padded layouts (A stride 80B, B 272B).
// blockIdx.z selects B/bias/C (QKV fusion).
// smem: As 4x10240 @0 | Bs 4x8704 @40960 | mbar x4 @75776
// ---------------------------------------------------------------------------
#define A_ST (128*40)    // halves per A stage
#define B_ST (32*136)    // halves per B stage

template<bool HALF_OUT>
__global__ __launch_bounds__(256, 2)
void gemm16(const __half* __restrict__ A,
            const __half* __restrict__ B0, const __half* __restrict__ B1, const __half* __restrict__ B2,
            const float* __restrict__ bias0, const float* __restrict__ bias1, const float* __restrict__ bias2,
            void* __restrict__ C0, void* __restrict__ C1, void* __restrict__ C2)
{
    extern __shared__ __align__(128) __half gsm[];
    __half* As = gsm;               // [4][128][40]
    __half* Bs = gsm + 4 * A_ST;    // [4][32][136]
    const uint32_t mbar = smem_u32(gsm) + 75776;

    const __half* B;
    const float* bias;
    void* Cout;
    if (blockIdx.z == 0)      { B = B0; bias = bias0; Cout = C0; }
    else if (blockIdx.z == 1) { B = B1; bias = bias1; Cout = C1; }
    else                      { B = B2; bias = bias2; Cout = C2; }

    const int tid  = threadIdx.x;
    const int lane = tid & 31;
    const int wid  = tid >> 5;
    const int g    = lane >> 2;
    const int t    = lane & 3;
    const int warp_m = wid >> 2;   // 0..1
    const int warp_n = wid & 3;    // 0..3
    const int bm = blockIdx.y * 128;
    const int bn = blockIdx.x * 128;
    const int NKT = HH / 32;       // 32

    auto load_tile = [&](int kt, int st) {
        int k0 = kt * 32;
        if (tid == 0) MBARRIER_EXPECT_TX(mbar + st * 8, 16384);
        if (tid < 128) {
            const __half* src = A + (size_t)(bm + tid) * HH + k0;
            BULK_G2S(smem_u32(As + st * A_ST + tid * 40), src, 64, mbar + st * 8);
        } else if (tid < 160) {
            int r = tid - 128;
            const __half* src = B + (size_t)(k0 + r) * HH + bn;
            BULK_G2S(smem_u32(Bs + st * B_ST + r * 136), src, 256, mbar + st * 8);
        }
    };

    if (tid == 0) {
#pragma unroll
        for (int s = 0; s < 4; s++) MBARRIER_INIT(mbar + s * 8, 1);
    }
    __syncthreads();
#pragma unroll
    for (int s = 0; s < 4; s++) load_tile(s, s);

    float acc[4][4][4];
#pragma unroll
    for (int mt = 0; mt < 4; mt++)
#pragma unroll
        for (int nt = 0; nt < 4; nt++)
#pragma unroll
            for (int i = 0; i < 4; i++) acc[mt][nt][i] = 0.0f;

    const uint32_t a_base = smem_u32(As) + (warp_m * 64 + (lane & 15)) * 80 + (lane >> 4) * 16;
    const uint32_t b_base = smem_u32(Bs) + (((lane >> 3) & 1) * 8 + (lane & 7)) * 272 +
                            (warp_n * 32 + (lane >> 4) * 8) * 2;

    for (int kt = 0; kt < NKT; kt++) {
        const int st = kt & 3;
        mbar_wait(mbar + st * 8, (uint32_t)((kt >> 2) & 1));

        const uint32_t asb = a_base + st * (A_ST * 2);
        const uint32_t bsb = b_base + st * (B_ST * 2);
#pragma unroll
        for (int ks = 0; ks < 2; ks++) {
            uint32_t a[4][4], bq[8];
#pragma unroll
            for (int mt = 0; mt < 4; mt++)
                ldsm4(a[mt], asb + mt * (16 * 80) + ks * 32);
#pragma unroll
            for (int np = 0; np < 2; np++)
                ldsm4t(&bq[4 * np], bsb + ks * (16 * 272) + np * 32);
#pragma unroll
            for (int mt = 0; mt < 4; mt++)
#pragma unroll
                for (int nt = 0; nt < 4; nt++)
                    mma16816(acc[mt][nt], a[mt], &bq[2 * nt]);
        }
        __syncthreads();
        if (kt + 4 < NKT) load_tile(kt + 4, st);
    }

    // Epilogue
#pragma unroll
    for (int mt = 0; mt < 4; mt++) {
        int row = bm + warp_m * 64 + mt * 16 + g;
#pragma unroll
        for (int nt = 0; nt < 4; nt++) {
            int col = bn + warp_n * 32 + nt * 8 + 2 * t;
            float2 bv = *(const float2*)(bias + col);
            float x0 = acc[mt][nt][0] + bv.x, x1 = acc[mt][nt][1] + bv.y;
            float x2 = acc[mt][nt][2] + bv.x, x3 = acc[mt][nt][3] + bv.y;
            if (HALF_OUT) {
                __half* C = (__half*)Cout;
                *(__half2*)(C + (size_t)row * HH + col)       = __floats2half2_rn(x0, x1);
                *(__half2*)(C + (size_t)(row + 8) * HH + col) = __floats2half2_rn(x2, x3);
            } else {
                float* C = (float*)Cout;
                *(float2*)(C + (size_t)row * HH + col)       = make_float2(x0, x1);
                *(float2*)(C + (size_t)(row + 8) * HH + col) = make_float2(x2, x3);
            }
        }
    }
}

// ---------------------------------------------------------------------------
// Bulk-fed flash attention: f16 mma, fp32 accum, register-resident P,
// no running max, h2exp2 softmax, l via P@ones mma — IDENTICAL math to the
// 502us kernel; only the K/V/mask fill changes (per-row cp.async.bulk into
// the proven 144B-stride layout, 4-stage mbarrier parity pipeline).
// Block = 8 warps x 16 Q rows. Grid (S/128, NH, B).
// smem: Qs[128][72] @0 | Ks 4x9216 @18432 | Vs 4x9216 @55296 |
//       Msk 4x256B @92160 | mbar x4 @93184
// ---------------------------------------------------------------------------
#define KV_ST_B (64*144)   // bytes per K (or V) stage

__global__ __launch_bounds__(256, 2)
void attn16(const __half* __restrict__ Qg, const __half* __restrict__ Kg,
            const __half* __restrict__ Vg, const float* __restrict__ maskg,
            __half* __restrict__ Ctx)
{
    extern __shared__ __align__(128) char smx[];
    __half* Qs  = (__half*)smx;                    // [128][72]
    __half* Ks  = (__half*)(smx + 18432);          // [4][64][72]
    __half* Vs  = (__half*)(smx + 55296);          // [4][64][72]
    float*  Msk = (float*)(smx + 92160);           // [4][64]
    const uint32_t mbar = smem_u32(smx) + 93184;

    const int tid  = threadIdx.x;
    const int lane = tid & 31;
    const int w    = tid >> 5;
    const int g    = lane >> 2;
    const int t    = lane & 3;
    const int qtile = blockIdx.x, h = blockIdx.y, b = blockIdx.z;
    const int tok0 = b * SS + qtile * 128;

    // one-time Q load via cp.async (proven layout, stride 72 halves)
    {
        int r = tid >> 1;
        const __half* src = Qg + (size_t)(tok0 + r) * HH + h * HDD;
        uint32_t dst = smem_u32(Qs + r * 72);
        int cb = (tid & 1) * 4;
#pragma unroll
        for (int j = 0; j < 4; j++) CP_ASYNC(dst + (cb + j) * 16, src + (cb + j) * 8);
        CP_COMMIT();
    }

    auto load_tile = [&](int kt, int st) {
        if (tid == 0) MBARRIER_EXPECT_TX(mbar + st * 8, 2 * 8192 + 256);
        if (tid < 64) {
            const __half* ks = Kg + (size_t)(b * SS + kt * 64 + tid) * HH + h * HDD;
            const __half* vs = Vg + (size_t)(b * SS + kt * 64 + tid) * HH + h * HDD;
            BULK_G2S(smem_u32(Ks) + st * KV_ST_B + tid * 144, ks, 128, mbar + st * 8);
            BULK_G2S(smem_u32(Vs) + st * KV_ST_B + tid * 144, vs, 128, mbar + st * 8);
        } else if (tid == 64) {
            BULK_G2S(smem_u32(Msk + st * 64), maskg + (size_t)b * SS + kt * 64, 256, mbar + st * 8);
        }
    };

    if (tid == 0) {
#pragma unroll
        for (int s = 0; s < 4; s++) MBARRIER_INIT(mbar + s * 8, 1);
    }
    __syncthreads();
#pragma unroll
    for (int s = 0; s < 4; s++) load_tile(s, s);

    CP_WAIT0();
    __syncthreads();

    // Q fragments, register-resident
    uint32_t qa[4][4];
    {
        uint32_t base = smem_u32(Qs + (16 * w + (lane & 15)) * 72 + (lane >> 4) * 8);
#pragma unroll
        for (int ks = 0; ks < 4; ks++) ldsm4(qa[ks], base + ks * 32);
    }

    float o[8][4];
#pragma unroll
    for (int nt = 0; nt < 8; nt++)
#pragma unroll
        for (int i = 0; i < 4; i++) o[nt][i] = 0.0f;
    float lacc[4] = {0.0f, 0.0f, 0.0f, 0.0f};
    const float SC2 = 0.125f * LOG2E;
    const uint32_t ONESH2 = 0x3C003C00u;
    const uint32_t onesb[2] = { ONESH2, ONESH2 };

    const uint32_t kfrag = smem_u32(Ks) + (lane & 7) * 144 + (lane >> 3) * 16;
    const uint32_t vfrag = smem_u32(Vs) + lane * 144;

    const int NKV = SS / 64;   // 32
    for (int kt = 0; kt < NKV; kt++) {
        const int st = kt & 3;
        mbar_wait(mbar + st * 8, (uint32_t)((kt >> 2) & 1));

        // ---- S = Q @ K^T ----
        float s[8][4];
        const uint32_t kb0 = kfrag + st * KV_ST_B;
#pragma unroll
        for (int nt = 0; nt < 8; nt++) {
#pragma unroll
            for (int i = 0; i < 4; i++) s[nt][i] = 0.0f;
            uint32_t bb[8];
            ldsm4(&bb[0], kb0 + nt * (8 * 144));
            ldsm4(&bb[4], kb0 + nt * (8 * 144) + 64);
#pragma unroll
            for (int ks = 0; ks < 4; ks++) mma16816(s[nt], qa[ks], &bb[2 * ks]);
        }

        // ---- scale + mask + half-precision exp2 ----
        const float* mp = Msk + st * 64;
        uint32_t pk[8][2];
#pragma unroll
        for (int nt = 0; nt < 8; nt++) {
            float2 mk = *(const float2*)(mp + 8 * nt + 2 * t);
            float mkx = mk.x * LOG2E, mky = mk.y * LOG2E;
            float x0 = fmaf(s[nt][0], SC2, mkx);
            float x1 = fmaf(s[nt][1], SC2, mky);
            float x2 = fmaf(s[nt][2], SC2, mkx);
            float x3 = fmaf(s[nt][3], SC2, mky);
            pk[nt][0] = h2_as_u32(h2exp2(__floats2half2_rn(x0, x1)));
            pk[nt][1] = h2_as_u32(h2exp2(__floats2half2_rn(x2, x3)));
        }

        // ---- O += P @ V ; l += P @ ones ----
        const uint32_t vb0 = vfrag + st * KV_ST_B;
#pragma unroll
        for (int nt = 0; nt < 8; nt++) {
            uint32_t vb[8];
            ldsm4t(&vb[0], vb0 + nt * 16);
            ldsm4t(&vb[4], vb0 + nt * 16 + 32 * 144);
#pragma unroll
            for (int kb = 0; kb < 4; kb++) {
                uint32_t pa[4] = { pk[2*kb][0], pk[2*kb][1], pk[2*kb+1][0], pk[2*kb+1][1] };
                mma16816(o[nt], pa, &vb[2 * kb]);
            }
        }
#pragma unroll
        for (int kb = 0; kb < 4; kb++) {
            uint32_t pa[4] = { pk[2*kb][0], pk[2*kb][1], pk[2*kb+1][0], pk[2*kb+1][1] };
            mma16816(lacc, pa, onesb);
        }

        __syncthreads();
        if (kt + 4 < NKV) load_tile(kt + 4, st);
    }

    // ---- epilogue: every lane holds full row sums in lacc ----
    float ilo = 1.0f / lacc[0], ihi = 1.0f / lacc[2];
    int row = tok0 + 16 * w + g;
    __half* cb0 = Ctx + (size_t)row * HH + h * HDD + 2 * t;
    __half* cb1 = cb0 + (size_t)8 * HH;
#pragma unroll
    for (int nt = 0; nt < 8; nt++) {
        *(__half2*)(cb0 + 8 * nt) = __floats2half2_rn(o[nt][0] * ilo, o[nt][1] * ilo);
        *(__half2*)(cb1 + 8 * nt) = __floats2half2_rn(o[nt][2] * ihi, o[nt][3] * ihi);
    }
}

// ---------------------------------------------------------------------------
// LayerNorm(hidden) * gamma + beta + query
// ---------------------------------------------------------------------------
__global__ __launch_bounds__(256)
void ln_residual_kernel(const float* __restrict__ Hd, const float* __restrict__ X,
                        const float* __restrict__ gamma, const float* __restrict__ beta,
                        float* __restrict__ out)
{
    const int row = blockIdx.x;
    const int tid = threadIdx.x;
    const size_t base = (size_t)row * HH;

    float4 hv = ((const float4*)(Hd + base))[tid];
    float s  = hv.x + hv.y + hv.z + hv.w;
    float sq = hv.x * hv.x + hv.y * hv.y + hv.z * hv.z + hv.w * hv.w;
#pragma unroll
    for (int off = 16; off > 0; off >>= 1) {
        s  += __shfl_down_sync(0xffffffffu, s,  off);
        sq += __shfl_down_sync(0xffffffffu, sq, off);
    }
    __shared__ float ws[8], wsq[8], stats[2];
    int wid = tid >> 5, lane = tid & 31;
    if (lane == 0) { ws[wid] = s; wsq[wid] = sq; }
    __syncthreads();
    if (tid == 0) {
        float S = 0.0f, SQ = 0.0f;
#pragma unroll
        for (int i = 0; i < 8; i++) { S += ws[i]; SQ += wsq[i]; }
        float mean = S * (1.0f / HH);
        float var  = SQ * (1.0f / HH) - mean * mean;
        stats[0] = mean;
        stats[1] = rsqrtf(var + 1e-12f);
    }
    __syncthreads();
    float mean = stats[0], rstd = stats[1];

    float4 gv = ((const float4*)gamma)[tid];
    float4 bv = ((const float4*)beta)[tid];
    float4 xv = ((const float4*)(X + base))[tid];
    float4 ov;
    ov.x = (hv.x - mean) * rstd * gv.x + bv.x + xv.x;
    ov.y = (hv.y - mean) * rstd * gv.y + bv.y + xv.y;
    ov.z = (hv.z - mean) * rstd * gv.z + bv.z + xv.z;
    ov.w = (hv.w - mean) * rstd * gv.w + bv.w + xv.w;
    ((float4*)(out + base))[tid] = ov;
}

// ---------------------------------------------------------------------------
extern "C" void kernel_launch(void* const* d_in, const int* in_sizes, int n_in,
                              void* d_out, int out_size)
{
    const float* query = (const float*)d_in[0];
    const float* mask  = (const float*)d_in[1];
    const float* Wq    = (const float*)d_in[2];
    const float* bq    = (const float*)d_in[3];
    const float* Wk    = (const float*)d_in[4];
    const float* bk    = (const float*)d_in[5];
    const float* Wv    = (const float*)d_in[6];
    const float* bv    = (const float*)d_in[7];
    const float* Wd    = (const float*)d_in[8];
    const float* bd    = (const float*)d_in[9];
    const float* gamma = (const float*)d_in[10];
    const float* beta  = (const float*)d_in[11];
    float* out = (float*)d_out;

    __half *Xh, *Wh, *Qh, *Kh, *Vh, *Ch;
    float* Hp;
    cudaGetSymbolAddress((void**)&Xh,  g_Xh);
    cudaGetSymbolAddress((void**)&Wh,  g_Wh);
    cudaGetSymbolAddress((void**)&Qh,  g_Qh);
    cudaGetSymbolAddress((void**)&Kh,  g_Kh);
    cudaGetSymbolAddress((void**)&Vh,  g_Vh);
    cudaGetSymbolAddress((void**)&Ch,  g_Ch);
    cudaGetSymbolAddress((void**)&Hp,  g_Hd);

    __half* Wqh = Wh + 0 * (size_t)HH * HH;
    __half* Wkh = Wh + 1 * (size_t)HH * HH;
    __half* Wvh = Wh + 2 * (size_t)HH * HH;
    __half* Wdh = Wh + 3 * (size_t)HH * HH;

    // fp32 -> fp16 prep
    f2h_kernel<<<TOT / 4 / 256, 256>>>((const float4*)query, (__half2*)Xh, TOT / 4);
    f2h_w_kernel<<<dim3(HH * HH / 4 / 256, 4), 256>>>(
        (const float4*)Wq, (const float4*)Wk, (const float4*)Wv, (const float4*)Wd, (__half2*)Wh);

    const int gsmem = 75776 + 64;   // 4-stage A+B + mbars
    cudaFuncSetAttribute(gemm16<true>,  cudaFuncAttributeMaxDynamicSharedMemorySize, gsmem);
    cudaFuncSetAttribute(gemm16<false>, cudaFuncAttributeMaxDynamicSharedMemorySize, gsmem);

    // fused QKV projection (z selects W/bias/dst)
    dim3 gq(HH / 128, ROWS / 128, 3);
    gemm16<true><<<gq, 256, gsmem>>>(Xh, Wqh, Wkh, Wvh, bq, bk, bv, Qh, Kh, Vh);

    // attention
    const int asmem = 93184 + 64;
    cudaFuncSetAttribute(attn16, cudaFuncAttributeMaxDynamicSharedMemorySize, asmem);
    attn16<<<dim3(SS / 128, NHH, BB), 256, asmem>>>(Qh, Kh, Vh, mask, Ch);

    // output projection (float out)
    dim3 gg(HH / 128, ROWS / 128, 1);
    gemm16<false><<<gg, 256, gsmem>>>(Ch, Wdh, nullptr, nullptr, bd, nullptr, nullptr,
                                      Hp, nullptr, nullptr);

    // LN + residual
    ln_residual_kernel<<<ROWS, 256>>>(Hp, query, gamma, beta, out);
}

// round 11
// speedup vs baseline: 1.3846x; 1.3846x over previous
#include <cuda_runtime.h>
#include <cuda_fp16.h>
#include <math.h>
#include <stdint.h>

#define BB   4
#define SS   2048
#define HH   1024
#define NHH  16
#define HDD  64
#define ROWS (BB*SS)            // 8192
#define TOT  (ROWS*HH)          // 8,388,608
#define LOG2E 1.4426950408889634f

// ---------------- device scratch (no allocs allowed) ----------------
__device__ __half g_Xh[TOT];
__device__ __half g_Wh[4][HH*HH];   // Wq, Wk, Wv, Wd (half)
__device__ __half g_Qh[TOT];
__device__ __half g_Kh[TOT];
__device__ __half g_Vh[TOT];
__device__ __half g_Ch[TOT];
__device__ float  g_Hd[TOT];

// ---------------- PTX helpers ----------------
__device__ __forceinline__ uint32_t smem_u32(const void* p) {
    return (uint32_t)__cvta_generic_to_shared(p);
}
__device__ __forceinline__ uint32_t h2_as_u32(__half2 h) {
    union { __half2 h2; uint32_t u; } cvt;
    cvt.h2 = h;
    return cvt.u;
}
#define CP_ASYNC(dst, src) asm volatile("cp.async.cg.shared.global [%0], [%1], 16;\n" :: "r"(dst), "l"(src))
#define CP_COMMIT()  asm volatile("cp.async.commit_group;\n")
#define CP_WAIT0()   asm volatile("cp.async.wait_group 0;\n")
#define CP_WAIT1()   asm volatile("cp.async.wait_group 1;\n")
#define CP_WAIT2()   asm volatile("cp.async.wait_group 2;\n")
#define CP_WAIT3()   asm volatile("cp.async.wait_group 3;\n")

__device__ __forceinline__ void ldsm4(uint32_t* r, uint32_t addr) {
    asm volatile("ldmatrix.sync.aligned.m8n8.x4.shared.b16 {%0,%1,%2,%3}, [%4];\n"
                 : "=r"(r[0]), "=r"(r[1]), "=r"(r[2]), "=r"(r[3]) : "r"(addr));
}
__device__ __forceinline__ void ldsm4t(uint32_t* r, uint32_t addr) {
    asm volatile("ldmatrix.sync.aligned.m8n8.x4.trans.shared.b16 {%0,%1,%2,%3}, [%4];\n"
                 : "=r"(r[0]), "=r"(r[1]), "=r"(r[2]), "=r"(r[3]) : "r"(addr));
}
__device__ __forceinline__ void mma16816(float* d, const uint32_t* a, const uint32_t* b) {
    asm volatile("mma.sync.aligned.m16n8k16.row.col.f32.f16.f16.f32 "
                 "{%0,%1,%2,%3}, {%4,%5,%6,%7}, {%8,%9}, {%0,%1,%2,%3};\n"
                 : "+f"(d[0]), "+f"(d[1]), "+f"(d[2]), "+f"(d[3])
                 : "r"(a[0]), "r"(a[1]), "r"(a[2]), "r"(a[3]), "r"(b[0]), "r"(b[1]));
}

// ---------------- fp32 -> fp16 conversions ----------------
__global__ void f2h_kernel(const float4* __restrict__ in, __half2* __restrict__ out, int n4) {
    int i = blockIdx.x * blockDim.x + threadIdx.x;
    if (i < n4) {
        float4 v = in[i];
        out[2*i + 0] = __floats2half2_rn(v.x, v.y);
        out[2*i + 1] = __floats2half2_rn(v.z, v.w);
    }
}
__global__ void f2h_w_kernel(const float4* __restrict__ w0, const float4* __restrict__ w1,
                             const float4* __restrict__ w2, const float4* __restrict__ w3,
                             __half2* __restrict__ out) {
    const float4* srcs[4] = { w0, w1, w2, w3 };
    const float4* src = srcs[blockIdx.y];
    __half2* dst = out + (size_t)blockIdx.y * (HH * HH / 2);
    int i = blockIdx.x * blockDim.x + threadIdx.x;
    float4 v = src[i];
    dst[2*i + 0] = __floats2half2_rn(v.x, v.y);
    dst[2*i + 1] = __floats2half2_rn(v.z, v.w);
}

// ---------------------------------------------------------------------------
// f16 GEMM: C[M,N] = A[M,K] @ B[K,N] + bias.
// Block tile 256x128, K-tile 32, 512 threads = 16 warps (4x4), warp 64x32.
// Doubled M-tile halves A traffic per FLOP. 4-stage cp.async, 1 CTA/SM.
// ---------------------------------------------------------------------------
#define A_ST (256*40)    // halves per A stage
#define B_ST (32*136)    // halves per B stage

template<bool HALF_OUT>
__global__ __launch_bounds__(512, 1)
void gemm16(const __half* __restrict__ A,
            const __half* __restrict__ B0, const __half* __restrict__ B1, const __half* __restrict__ B2,
            const float* __restrict__ bias0, const float* __restrict__ bias1, const float* __restrict__ bias2,
            void* __restrict__ C0, void* __restrict__ C1, void* __restrict__ C2)
{
    extern __shared__ __align__(128) __half gsm[];
    __half* As = gsm;               // [4][256][40]
    __half* Bs = gsm + 4 * A_ST;    // [4][32][136]

    const __half* B;
    const float* bias;
    void* Cout;
    if (blockIdx.z == 0)      { B = B0; bias = bias0; Cout = C0; }
    else if (blockIdx.z == 1) { B = B1; bias = bias1; Cout = C1; }
    else                      { B = B2; bias = bias2; Cout = C2; }

    const int tid  = threadIdx.x;
    const int lane = tid & 31;
    const int wid  = tid >> 5;     // 0..15
    const int g    = lane >> 2;
    const int t    = lane & 3;
    const int warp_m = wid >> 2;   // 0..3 (64 rows each)
    const int warp_n = wid & 3;    // 0..3 (32 cols each)
    const int bm = blockIdx.y * 256;
    const int bn = blockIdx.x * 128;
    const int NKT = HH / 32;       // 32

    const int arow = tid >> 1;           // 0..255
    const int acb  = (tid & 1) * 2;
    const int br   = tid >> 4;           // 0..31
    const int bc   = tid & 15;           // 0..15

    auto load_tile = [&](int kt, int st) {
        int k0 = kt * 32;
        const __half* asrc = A + (size_t)(bm + arow) * HH + k0;
        uint32_t adst = smem_u32(As + st * A_ST + arow * 40);
        CP_ASYNC(adst + (acb + 0) * 16, asrc + (acb + 0) * 8);
        CP_ASYNC(adst + (acb + 1) * 16, asrc + (acb + 1) * 8);
        CP_ASYNC(smem_u32(Bs + st * B_ST + br * 136 + bc * 8),
                 B + (size_t)(k0 + br) * HH + bn + bc * 8);
    };

    float acc[4][4][4];
#pragma unroll
    for (int mt = 0; mt < 4; mt++)
#pragma unroll
        for (int nt = 0; nt < 4; nt++)
#pragma unroll
            for (int i = 0; i < 4; i++) acc[mt][nt][i] = 0.0f;

    load_tile(0, 0); CP_COMMIT();
    load_tile(1, 1); CP_COMMIT();
    load_tile(2, 2); CP_COMMIT();
    CP_WAIT2();
    __syncthreads();

    const uint32_t a_base = smem_u32(As) + (warp_m * 64 + (lane & 15)) * 80 + (lane >> 4) * 16;
    const uint32_t b_base = smem_u32(Bs) + (((lane >> 3) & 1) * 8 + (lane & 7)) * 272 +
                            (warp_n * 32 + (lane >> 4) * 8) * 2;

    for (int kt = 0; kt < NKT; kt += 4) {
#pragma unroll
        for (int j = 0; j < 4; j++) {
            if (kt + j + 3 < NKT)      { load_tile(kt + j + 3, (j + 3) & 3); CP_COMMIT(); CP_WAIT3(); }
            else if (kt + j + 2 < NKT) { CP_WAIT2(); }
            else if (kt + j + 1 < NKT) { CP_WAIT1(); }
            else                       { CP_WAIT0(); }

            const uint32_t asb = a_base + j * (A_ST * 2);
            const uint32_t bsb = b_base + j * (B_ST * 2);
#pragma unroll
            for (int ks = 0; ks < 2; ks++) {
                uint32_t a[4][4], bq[8];
#pragma unroll
                for (int mt = 0; mt < 4; mt++)
                    ldsm4(a[mt], asb + mt * (16 * 80) + ks * 32);
#pragma unroll
                for (int np = 0; np < 2; np++)
                    ldsm4t(&bq[4 * np], bsb + ks * (16 * 272) + np * 32);
#pragma unroll
                for (int mt = 0; mt < 4; mt++)
#pragma unroll
                    for (int nt = 0; nt < 4; nt++)
                        mma16816(acc[mt][nt], a[mt], &bq[2 * nt]);
            }
            __syncthreads();
        }
    }

    // Epilogue
#pragma unroll
    for (int mt = 0; mt < 4; mt++) {
        int row = bm + warp_m * 64 + mt * 16 + g;
#pragma unroll
        for (int nt = 0; nt < 4; nt++) {
            int col = bn + warp_n * 32 + nt * 8 + 2 * t;
            float2 bv = *(const float2*)(bias + col);
            float x0 = acc[mt][nt][0] + bv.x, x1 = acc[mt][nt][1] + bv.y;
            float x2 = acc[mt][nt][2] + bv.x, x3 = acc[mt][nt][3] + bv.y;
            if (HALF_OUT) {
                __half* C = (__half*)Cout;
                *(__half2*)(C + (size_t)row * HH + col)       = __floats2half2_rn(x0, x1);
                *(__half2*)(C + (size_t)(row + 8) * HH + col) = __floats2half2_rn(x2, x3);
            } else {
                float* C = (float*)Cout;
                *(float2*)(C + (size_t)row * HH + col)       = make_float2(x0, x1);
                *(float2*)(C + (size_t)(row + 8) * HH + col) = make_float2(x2, x3);
            }
        }
    }
}

// ---------------------------------------------------------------------------
// Flash attention: 256 Q rows/CTA (16 warps x 16 rows), 512 threads, 1 CTA/SM.
// Halves total K/V global traffic (the measured LDGSTS binder) vs 128-row CTAs.
// Per-warp inner loop byte-identical to the proven 502us kernel:
// register-resident P, no running max, h2exp2, l via P@ones mma,
// 4-stage cp.async K/V pipeline. Grid: (S/256, NH, B).
// smem: Qs[256][72] @0 | Ks 4x9216 @36864 | Vs 4x9216 @73728 | Msk @110592
// ---------------------------------------------------------------------------
#define KV_ST   (64*72)
#define KV_ST_B (KV_ST*2)

__global__ __launch_bounds__(512, 1)
void attn16(const __half* __restrict__ Qg, const __half* __restrict__ Kg,
            const __half* __restrict__ Vg, const float* __restrict__ maskg,
            __half* __restrict__ Ctx)
{
    extern __shared__ __align__(128) char smx[];
    __half* Qs  = (__half*)smx;                    // [256][72]
    __half* Ks  = (__half*)(smx + 36864);          // [4][64][72]
    __half* Vs  = (__half*)(smx + 73728);          // [4][64][72]
    float*  Msk = (float*)(smx + 110592);          // [4][64]

    const int tid  = threadIdx.x;
    const int lane = tid & 31;
    const int w    = tid >> 5;    // 0..15, 16 Q rows each
    const int g    = lane >> 2;
    const int t    = lane & 3;
    const int qtile = blockIdx.x, h = blockIdx.y, b = blockIdx.z;
    const int tok0 = b * SS + qtile * 256;

    // Q load: 256 rows x 64 halves (one half-row per thread)
    {
        int r = tid >> 1;
        const __half* src = Qg + (size_t)(tok0 + r) * HH + h * HDD;
        uint32_t dst = smem_u32(Qs + r * 72);
        int cb = (tid & 1) * 4;
#pragma unroll
        for (int j = 0; j < 4; j++) CP_ASYNC(dst + (cb + j) * 16, src + (cb + j) * 8);
    }

    auto load_tile = [&](int kt, int st) {
        int r  = tid >> 3;          // 0..63
        int cb = tid & 7;           // chunk 0..7
        const __half* ks = Kg + (size_t)(b * SS + kt * 64 + r) * HH + h * HDD;
        const __half* vs = Vg + (size_t)(b * SS + kt * 64 + r) * HH + h * HDD;
        CP_ASYNC(smem_u32(Ks) + st * KV_ST_B + r * 144 + cb * 16, ks + cb * 8);
        CP_ASYNC(smem_u32(Vs) + st * KV_ST_B + r * 144 + cb * 16, vs + cb * 8);
        if (tid < 16)
            CP_ASYNC(smem_u32(Msk + st * 64 + tid * 4), maskg + (size_t)b * SS + kt * 64 + tid * 4);
    };

    load_tile(0, 0); CP_COMMIT();
    load_tile(1, 1); CP_COMMIT();
    load_tile(2, 2); CP_COMMIT();
    CP_WAIT2();
    __syncthreads();

    // Q fragments, register-resident
    uint32_t qa[4][4];
    {
        uint32_t base = smem_u32(Qs + (16 * w + (lane & 15)) * 72 + (lane >> 4) * 8);
#pragma unroll
        for (int ks = 0; ks < 4; ks++) ldsm4(qa[ks], base + ks * 32);
    }

    float o[8][4];
#pragma unroll
    for (int nt = 0; nt < 8; nt++)
#pragma unroll
        for (int i = 0; i < 4; i++) o[nt][i] = 0.0f;
    float lacc[4] = {0.0f, 0.0f, 0.0f, 0.0f};
    const float SC2 = 0.125f * LOG2E;
    const uint32_t ONESH2 = 0x3C003C00u;
    const uint32_t onesb[2] = { ONESH2, ONESH2 };

    const uint32_t kfrag = smem_u32(Ks) + (lane & 7) * 144 + (lane >> 3) * 16;
    const uint32_t vfrag = smem_u32(Vs) + lane * 144;

    const int NKV = SS / 64;   // 32
    for (int kt = 0; kt < NKV; kt += 4) {
#pragma unroll
        for (int j = 0; j < 4; j++) {
            if (kt + j + 3 < NKV)      { load_tile(kt + j + 3, (j + 3) & 3); CP_COMMIT(); CP_WAIT3(); }
            else if (kt + j + 2 < NKV) { CP_WAIT2(); }
            else if (kt + j + 1 < NKV) { CP_WAIT1(); }
            else                       { CP_WAIT0(); }

            // ---- S = Q @ K^T ----
            float s[8][4];
            const uint32_t kb0 = kfrag + j * KV_ST_B;
#pragma unroll
            for (int nt = 0; nt < 8; nt++) {
#pragma unroll
                for (int i = 0; i < 4; i++) s[nt][i] = 0.0f;
                uint32_t bb[8];
                ldsm4(&bb[0], kb0 + nt * (8 * 144));
                ldsm4(&bb[4], kb0 + nt * (8 * 144) + 64);
#pragma unroll
                for (int ks = 0; ks < 4; ks++) mma16816(s[nt], qa[ks], &bb[2 * ks]);
            }

            // ---- scale + mask + half-precision exp2 ----
            const float* mp = Msk + j * 64;
            uint32_t pk[8][2];
#pragma unroll
            for (int nt = 0; nt < 8; nt++) {
                float2 mk = *(const float2*)(mp + 8 * nt + 2 * t);
                float mkx = mk.x * LOG2E, mky = mk.y * LOG2E;
                float x0 = fmaf(s[nt][0], SC2, mkx);
                float x1 = fmaf(s[nt][1], SC2, mky);
                float x2 = fmaf(s[nt][2], SC2, mkx);
                float x3 = fmaf(s[nt][3], SC2, mky);
                pk[nt][0] = h2_as_u32(h2exp2(__floats2half2_rn(x0, x1)));
                pk[nt][1] = h2_as_u32(h2exp2(__floats2half2_rn(x2, x3)));
            }

            // ---- O += P @ V ; l += P @ ones ----
            const uint32_t vb0 = vfrag + j * KV_ST_B;
#pragma unroll
            for (int nt = 0; nt < 8; nt++) {
                uint32_t vb[8];
                ldsm4t(&vb[0], vb0 + nt * 16);
                ldsm4t(&vb[4], vb0 + nt * 16 + 32 * 144);
#pragma unroll
                for (int kb = 0; kb < 4; kb++) {
                    uint32_t pa[4] = { pk[2*kb][0], pk[2*kb][1], pk[2*kb+1][0], pk[2*kb+1][1] };
                    mma16816(o[nt], pa, &vb[2 * kb]);
                }
            }
#pragma unroll
            for (int kb = 0; kb < 4; kb++) {
                uint32_t pa[4] = { pk[2*kb][0], pk[2*kb][1], pk[2*kb+1][0], pk[2*kb+1][1] };
                mma16816(lacc, pa, onesb);
            }
            __syncthreads();
        }
    }

    // ---- epilogue: every lane holds full row sums in lacc ----
    float ilo = 1.0f / lacc[0], ihi = 1.0f / lacc[2];
    int row = tok0 + 16 * w + g;
    __half* cb0 = Ctx + (size_t)row * HH + h * HDD + 2 * t;
    __half* cb1 = cb0 + (size_t)8 * HH;
#pragma unroll
    for (int nt = 0; nt < 8; nt++) {
        *(__half2*)(cb0 + 8 * nt) = __floats2half2_rn(o[nt][0] * ilo, o[nt][1] * ilo);
        *(__half2*)(cb1 + 8 * nt) = __floats2half2_rn(o[nt][2] * ihi, o[nt][3] * ihi);
    }
}

// ---------------------------------------------------------------------------
// LayerNorm(hidden) * gamma + beta + query
// ---------------------------------------------------------------------------
__global__ __launch_bounds__(256)
void ln_residual_kernel(const float* __restrict__ Hd, const float* __restrict__ X,
                        const float* __restrict__ gamma, const float* __restrict__ beta,
                        float* __restrict__ out)
{
    const int row = blockIdx.x;
    const int tid = threadIdx.x;
    const size_t base = (size_t)row * HH;

    float4 hv = ((const float4*)(Hd + base))[tid];
    float s  = hv.x + hv.y + hv.z + hv.w;
    float sq = hv.x * hv.x + hv.y * hv.y + hv.z * hv.z + hv.w * hv.w;
#pragma unroll
    for (int off = 16; off > 0; off >>= 1) {
        s  += __shfl_down_sync(0xffffffffu, s,  off);
        sq += __shfl_down_sync(0xffffffffu, sq, off);
    }
    __shared__ float ws[8], wsq[8], stats[2];
    int wid = tid >> 5, lane = tid & 31;
    if (lane == 0) { ws[wid] = s; wsq[wid] = sq; }
    __syncthreads();
    if (tid == 0) {
        float S = 0.0f, SQ = 0.0f;
#pragma unroll
        for (int i = 0; i < 8; i++) { S += ws[i]; SQ += wsq[i]; }
        float mean = S * (1.0f / HH);
        float var  = SQ * (1.0f / HH) - mean * mean;
        stats[0] = mean;
        stats[1] = rsqrtf(var + 1e-12f);
    }
    __syncthreads();
    float mean = stats[0], rstd = stats[1];

    float4 gv = ((const float4*)gamma)[tid];
    float4 bv = ((const float4*)beta)[tid];
    float4 xv = ((const float4*)(X + base))[tid];
    float4 ov;
    ov.x = (hv.x - mean) * rstd * gv.x + bv.x + xv.x;
    ov.y = (hv.y - mean) * rstd * gv.y + bv.y + xv.y;
    ov.z = (hv.z - mean) * rstd * gv.z + bv.z + xv.z;
    ov.w = (hv.w - mean) * rstd * gv.w + bv.w + xv.w;
    ((float4*)(out + base))[tid] = ov;
}

// ---------------------------------------------------------------------------
extern "C" void kernel_launch(void* const* d_in, const int* in_sizes, int n_in,
                              void* d_out, int out_size)
{
    const float* query = (const float*)d_in[0];
    const float* mask  = (const float*)d_in[1];
    const float* Wq    = (const float*)d_in[2];
    const float* bq    = (const float*)d_in[3];
    const float* Wk    = (const float*)d_in[4];
    const float* bk    = (const float*)d_in[5];
    const float* Wv    = (const float*)d_in[6];
    const float* bv    = (const float*)d_in[7];
    const float* Wd    = (const float*)d_in[8];
    const float* bd    = (const float*)d_in[9];
    const float* gamma = (const float*)d_in[10];
    const float* beta  = (const float*)d_in[11];
    float* out = (float*)d_out;

    __half *Xh, *Wh, *Qh, *Kh, *Vh, *Ch;
    float* Hp;
    cudaGetSymbolAddress((void**)&Xh,  g_Xh);
    cudaGetSymbolAddress((void**)&Wh,  g_Wh);
    cudaGetSymbolAddress((void**)&Qh,  g_Qh);
    cudaGetSymbolAddress((void**)&Kh,  g_Kh);
    cudaGetSymbolAddress((void**)&Vh,  g_Vh);
    cudaGetSymbolAddress((void**)&Ch,  g_Ch);
    cudaGetSymbolAddress((void**)&Hp,  g_Hd);

    __half* Wqh = Wh + 0 * (size_t)HH * HH;
    __half* Wkh = Wh + 1 * (size_t)HH * HH;
    __half* Wvh = Wh + 2 * (size_t)HH * HH;
    __half* Wdh = Wh + 3 * (size_t)HH * HH;

    // fp32 -> fp16 prep
    f2h_kernel<<<TOT / 4 / 256, 256>>>((const float4*)query, (__half2*)Xh, TOT / 4);
    f2h_w_kernel<<<dim3(HH * HH / 4 / 256, 4), 256>>>(
        (const float4*)Wq, (const float4*)Wk, (const float4*)Wv, (const float4*)Wd, (__half2*)Wh);

    const int gsmem = (4 * A_ST + 4 * B_ST) * 2;   // 116,736 B
    cudaFuncSetAttribute(gemm16<true>,  cudaFuncAttributeMaxDynamicSharedMemorySize, gsmem);
    cudaFuncSetAttribute(gemm16<false>, cudaFuncAttributeMaxDynamicSharedMemorySize, gsmem);

    // fused QKV projection (z selects W/bias/dst), 256-row M tiles
    dim3 gq(HH / 128, ROWS / 256, 3);   // (8, 32, 3)
    gemm16<true><<<gq, 512, gsmem>>>(Xh, Wqh, Wkh, Wvh, bq, bk, bv, Qh, Kh, Vh);

    // attention: 256 Q rows per CTA
    const int asmem = 110592 + 1024;   // 111,616 B
    cudaFuncSetAttribute(attn16, cudaFuncAttributeMaxDynamicSharedMemorySize, asmem);
    attn16<<<dim3(SS / 256, NHH, BB), 512, asmem>>>(Qh, Kh, Vh, mask, Ch);

    // output projection (float out)
    dim3 gg(HH / 128, ROWS / 256, 1);
    gemm16<false><<<gg, 512, gsmem>>>(Ch, Wdh, nullptr, nullptr, bd, nullptr, nullptr,
                                      Hp, nullptr, nullptr);

    // LN + residual
    ln_residual_kernel<<<ROWS, 256>>>(Hp, query, gamma, beta, out);
}

// round 13
// speedup vs baseline: 1.4304x; 1.0331x over previous
#include <cuda_runtime.h>
#include <cuda_fp16.h>
#include <math.h>
#include <stdint.h>

#define BB   4
#define SS   2048
#define HH   1024
#define NHH  16
#define HDD  64
#define ROWS (BB*SS)            // 8192
#define TOT  (ROWS*HH)          // 8,388,608
#define LOG2E 1.4426950408889634f

// ---------------- device scratch (no allocs allowed) ----------------
__device__ __half g_Xh[TOT];
__device__ __half g_Wh[4][HH*HH];   // Wq, Wk, Wv, Wd (half)
__device__ __half g_Qh[TOT];
__device__ __half g_Kh[TOT];
__device__ __half g_Vh[TOT];
__device__ __half g_Ch[TOT];
__device__ float  g_Hd[TOT];

// ---------------- PTX helpers ----------------
__device__ __forceinline__ uint32_t smem_u32(const void* p) {
    return (uint32_t)__cvta_generic_to_shared(p);
}
__device__ __forceinline__ uint32_t h2_as_u32(__half2 h) {
    union { __half2 h2; uint32_t u; } cvt;
    cvt.h2 = h;
    return cvt.u;
}
#define CP_ASYNC(dst, src) asm volatile("cp.async.cg.shared.global [%0], [%1], 16;\n" :: "r"(dst), "l"(src))
#define CP_COMMIT()  asm volatile("cp.async.commit_group;\n")
#define CP_WAIT0()   asm volatile("cp.async.wait_group 0;\n")
#define CP_WAIT1()   asm volatile("cp.async.wait_group 1;\n")
#define CP_WAIT2()   asm volatile("cp.async.wait_group 2;\n")
#define CP_WAIT3()   asm volatile("cp.async.wait_group 3;\n")

__device__ __forceinline__ void ldsm4(uint32_t* r, uint32_t addr) {
    asm volatile("ldmatrix.sync.aligned.m8n8.x4.shared.b16 {%0,%1,%2,%3}, [%4];\n"
                 : "=r"(r[0]), "=r"(r[1]), "=r"(r[2]), "=r"(r[3]) : "r"(addr));
}
__device__ __forceinline__ void ldsm4t(uint32_t* r, uint32_t addr) {
    asm volatile("ldmatrix.sync.aligned.m8n8.x4.trans.shared.b16 {%0,%1,%2,%3}, [%4];\n"
                 : "=r"(r[0]), "=r"(r[1]), "=r"(r[2]), "=r"(r[3]) : "r"(addr));
}
__device__ __forceinline__ void mma16816(float* d, const uint32_t* a, const uint32_t* b) {
    asm volatile("mma.sync.aligned.m16n8k16.row.col.f32.f16.f16.f32 "
                 "{%0,%1,%2,%3}, {%4,%5,%6,%7}, {%8,%9}, {%0,%1,%2,%3};\n"
                 : "+f"(d[0]), "+f"(d[1]), "+f"(d[2]), "+f"(d[3])
                 : "r"(a[0]), "r"(a[1]), "r"(a[2]), "r"(a[3]), "r"(b[0]), "r"(b[1]));
}

// ---------------- fp32 -> fp16 conversions ----------------
__global__ void f2h_kernel(const float4* __restrict__ in, __half2* __restrict__ out, int n4) {
    int i = blockIdx.x * blockDim.x + threadIdx.x;
    if (i < n4) {
        float4 v = in[i];
        out[2*i + 0] = __floats2half2_rn(v.x, v.y);
        out[2*i + 1] = __floats2half2_rn(v.z, v.w);
    }
}
__global__ void f2h_w_kernel(const float4* __restrict__ w0, const float4* __restrict__ w1,
                             const float4* __restrict__ w2, const float4* __restrict__ w3,
                             __half2* __restrict__ out) {
    const float4* srcs[4] = { w0, w1, w2, w3 };
    const float4* src = srcs[blockIdx.y];
    __half2* dst = out + (size_t)blockIdx.y * (HH * HH / 2);
    int i = blockIdx.x * blockDim.x + threadIdx.x;
    float4 v = src[i];
    dst[2*i + 0] = __floats2half2_rn(v.x, v.y);
    dst[2*i + 1] = __floats2half2_rn(v.z, v.w);
}

// ---------------------------------------------------------------------------
// FUSED QKV GEMM: Q/K/V = X @ {Wq,Wk,Wv} + bias, one CTA computes all three
// for a 128(M) x 128(N) tile. A(X) tile loaded ONCE per kt, shared by 3 mma
// streams (-33% LDGSTS bytes, A-fragment reuse 6x, B-fragment reuse 4x).
// 512 threads = 16 warps (2 m x 8 n), warp tile 64x16 per weight.
// 4-stage cp.async pipeline, 1 CTA/SM.
// smem: A [4][128][40] | B [3 weights][4 stages][32][136]
// ---------------------------------------------------------------------------
#define A_STQ (128*40)
#define B_STQ (32*136)

__global__ __launch_bounds__(512, 1)
void gemm_qkv(const __half* __restrict__ A,
              const __half* __restrict__ B0, const __half* __restrict__ B1,
              const __half* __restrict__ B2,
              const float* __restrict__ bias0, const float* __restrict__ bias1,
              const float* __restrict__ bias2,
              __half* __restrict__ C0, __half* __restrict__ C1, __half* __restrict__ C2)
{
    extern __shared__ __half gsm[];
    __half* As = gsm;                  // [4][128][40]
    __half* Bs = gsm + 4 * A_STQ;      // [3][4][32][136]

    const int tid  = threadIdx.x;
    const int lane = tid & 31;
    const int wid  = tid >> 5;       // 0..15
    const int g    = lane >> 2;
    const int t    = lane & 3;
    const int warp_m = wid & 1;      // 0..1 (64 rows)
    const int warp_n = wid >> 1;     // 0..7 (16 cols)
    const int bm = blockIdx.y * 128;
    const int bn = blockIdx.x * 128;
    const int NKT = HH / 32;         // 32

    const __half* Bw[3] = { B0, B1, B2 };

    // loads: 1 A chunk + 3 B chunks per thread per kt
    const int ar = tid >> 2, ac = tid & 3;        // A: 128 rows x 4 chunks
    const int brr = tid >> 4, bcc = tid & 15;     // B: 32 rows x 16 chunks

    auto load_tile = [&](int kt, int st) {
        int k0 = kt * 32;
        CP_ASYNC(smem_u32(As + st * A_STQ + ar * 40 + ac * 8),
                 A + (size_t)(bm + ar) * HH + k0 + ac * 8);
#pragma unroll
        for (int w = 0; w < 3; w++)
            CP_ASYNC(smem_u32(Bs + (w * 4 + st) * B_STQ + brr * 136 + bcc * 8),
                     Bw[w] + (size_t)(k0 + brr) * HH + bn + bcc * 8);
    };

    float acc[3][4][2][4];
#pragma unroll
    for (int w = 0; w < 3; w++)
#pragma unroll
        for (int mt = 0; mt < 4; mt++)
#pragma unroll
            for (int nt = 0; nt < 2; nt++)
#pragma unroll
                for (int i = 0; i < 4; i++) acc[w][mt][nt][i] = 0.0f;

    load_tile(0, 0); CP_COMMIT();
    load_tile(1, 1); CP_COMMIT();
    load_tile(2, 2); CP_COMMIT();
    CP_WAIT2();
    __syncthreads();

    const uint32_t a_base = smem_u32(As) + (warp_m * 64 + (lane & 15)) * 80 + (lane >> 4) * 16;
    const uint32_t b_base = smem_u32(Bs) + (((lane >> 3) & 1) * 8 + (lane & 7)) * 272 +
                            (warp_n * 16 + (lane >> 4) * 8) * 2;

    for (int kt = 0; kt < NKT; kt += 4) {
#pragma unroll
        for (int j = 0; j < 4; j++) {
            if (kt + j + 3 < NKT)      { load_tile(kt + j + 3, (j + 3) & 3); CP_COMMIT(); CP_WAIT3(); }
            else if (kt + j + 2 < NKT) { CP_WAIT2(); }
            else if (kt + j + 1 < NKT) { CP_WAIT1(); }
            else                       { CP_WAIT0(); }

            const uint32_t asb = a_base + j * (A_STQ * 2);
#pragma unroll
            for (int ks = 0; ks < 2; ks++) {
                uint32_t a[4][4];
#pragma unroll
                for (int mt = 0; mt < 4; mt++)
                    ldsm4(a[mt], asb + mt * (16 * 80) + ks * 32);
#pragma unroll
                for (int w = 0; w < 3; w++) {
                    uint32_t bq[4];
                    ldsm4t(bq, b_base + (w * 4 + j) * (B_STQ * 2) + ks * (16 * 272));
#pragma unroll
                    for (int mt = 0; mt < 4; mt++) {
                        mma16816(acc[w][mt][0], a[mt], &bq[0]);
                        mma16816(acc[w][mt][1], a[mt], &bq[2]);
                    }
                }
            }
            __syncthreads();
        }
    }

    // Epilogue: three half outputs
    const float* biases[3] = { bias0, bias1, bias2 };
    __half* Cs[3] = { C0, C1, C2 };
#pragma unroll
    for (int w = 0; w < 3; w++) {
#pragma unroll
        for (int mt = 0; mt < 4; mt++) {
            int row = bm + warp_m * 64 + mt * 16 + g;
#pragma unroll
            for (int nt = 0; nt < 2; nt++) {
                int col = bn + warp_n * 16 + nt * 8 + 2 * t;
                float2 bv = *(const float2*)(biases[w] + col);
                __half* C = Cs[w];
                *(__half2*)(C + (size_t)row * HH + col) =
                    __floats2half2_rn(acc[w][mt][nt][0] + bv.x, acc[w][mt][nt][1] + bv.y);
                *(__half2*)(C + (size_t)(row + 8) * HH + col) =
                    __floats2half2_rn(acc[w][mt][nt][2] + bv.x, acc[w][mt][nt][3] + bv.y);
            }
        }
    }
}

// ---------------------------------------------------------------------------
// f16 GEMM (out-projection, PROVEN R7 version): C = A @ B + bias, float out.
// Block 128x128, K-tile 32, 256 threads = 8 warps (2x4), warp 64x32.
// 4-stage cp.async, 2 CTAs/SM.
// ---------------------------------------------------------------------------
#define A_ST (128*40)
#define B_ST (32*136)

__global__ __launch_bounds__(256, 2)
void gemm16(const __half* __restrict__ A, const __half* __restrict__ B,
            const float* __restrict__ bias, float* __restrict__ Cout)
{
    extern __shared__ __half gsm[];
    __half* As = gsm;               // [4][128][40]
    __half* Bs = gsm + 4 * A_ST;    // [4][32][136]

    const int tid  = threadIdx.x;
    const int lane = tid & 31;
    const int wid  = tid >> 5;
    const int g    = lane >> 2;
    const int t    = lane & 3;
    const int warp_m = wid >> 2;
    const int warp_n = wid & 3;
    const int bm = blockIdx.y * 128;
    const int bn = blockIdx.x * 128;
    const int NKT = HH / 32;

    const int arow = tid >> 1;
    const int acb  = (tid & 1) * 2;
    const int brow = tid >> 4;
    const int bc   = tid & 15;

    auto load_tile = [&](int kt, int st) {
        int k0 = kt * 32;
        const __half* asrc = A + (size_t)(bm + arow) * HH + k0;
        uint32_t adst = smem_u32(As + st * A_ST + arow * 40);
        CP_ASYNC(adst + (acb + 0) * 16, asrc + (acb + 0) * 8);
        CP_ASYNC(adst + (acb + 1) * 16, asrc + (acb + 1) * 8);
        const __half* bsrc0 = B + (size_t)(k0 + brow) * HH + bn + bc * 8;
        const __half* bsrc1 = B + (size_t)(k0 + brow + 16) * HH + bn + bc * 8;
        CP_ASYNC(smem_u32(Bs + st * B_ST + brow * 136 + bc * 8), bsrc0);
        CP_ASYNC(smem_u32(Bs + st * B_ST + (brow + 16) * 136 + bc * 8), bsrc1);
    };

    float acc[4][4][4];
#pragma unroll
    for (int mt = 0; mt < 4; mt++)
#pragma unroll
        for (int nt = 0; nt < 4; nt++)
#pragma unroll
            for (int i = 0; i < 4; i++) acc[mt][nt][i] = 0.0f;

    load_tile(0, 0); CP_COMMIT();
    load_tile(1, 1); CP_COMMIT();
    load_tile(2, 2); CP_COMMIT();
    CP_WAIT2();
    __syncthreads();

    const uint32_t a_base = smem_u32(As) + (warp_m * 64 + (lane & 15)) * 80 + (lane >> 4) * 16;
    const uint32_t b_base = smem_u32(Bs) + (((lane >> 3) & 1) * 8 + (lane & 7)) * 272 +
                            (warp_n * 32 + (lane >> 4) * 8) * 2;

    for (int kt = 0; kt < NKT; kt += 4) {
#pragma unroll
        for (int j = 0; j < 4; j++) {
            if (kt + j + 3 < NKT)      { load_tile(kt + j + 3, (j + 3) & 3); CP_COMMIT(); CP_WAIT3(); }
            else if (kt + j + 2 < NKT) { CP_WAIT2(); }
            else if (kt + j + 1 < NKT) { CP_WAIT1(); }
            else                       { CP_WAIT0(); }

            const uint32_t asb = a_base + j * (A_ST * 2);
            const uint32_t bsb = b_base + j * (B_ST * 2);
#pragma unroll
            for (int ks = 0; ks < 2; ks++) {
                uint32_t a[4][4], bq[8];
#pragma unroll
                for (int mt = 0; mt < 4; mt++)
                    ldsm4(a[mt], asb + mt * (16 * 80) + ks * 32);
#pragma unroll
                for (int np = 0; np < 2; np++)
                    ldsm4t(&bq[4 * np], bsb + ks * (16 * 272) + np * 32);
#pragma unroll
                for (int mt = 0; mt < 4; mt++)
#pragma unroll
                    for (int nt = 0; nt < 4; nt++)
                        mma16816(acc[mt][nt], a[mt], &bq[2 * nt]);
            }
            __syncthreads();
        }
    }

#pragma unroll
    for (int mt = 0; mt < 4; mt++) {
        int row = bm + warp_m * 64 + mt * 16 + g;
#pragma unroll
        for (int nt = 0; nt < 4; nt++) {
            int col = bn + warp_n * 32 + nt * 8 + 2 * t;
            float2 bv = *(const float2*)(bias + col);
            *(float2*)(Cout + (size_t)row * HH + col) =
                make_float2(acc[mt][nt][0] + bv.x, acc[mt][nt][1] + bv.y);
            *(float2*)(Cout + (size_t)(row + 8) * HH + col) =
                make_float2(acc[mt][nt][2] + bv.x, acc[mt][nt][3] + bv.y);
        }
    }
}

// ---------------------------------------------------------------------------
// Flash attention (PROVEN 502us version): f16 mma.sync, fp32 accum,
// register-resident P, no running max, h2exp2, l via P@ones mma,
// 4-stage cp.async K/V pipeline. Block = 8 warps x 16 Q rows, 2 CTAs/SM.
// ---------------------------------------------------------------------------
#define KV_ST   (64*72)
#define KV_ST_B (KV_ST*2)

__global__ __launch_bounds__(256, 2)
void attn16(const __half* __restrict__ Qg, const __half* __restrict__ Kg,
            const __half* __restrict__ Vg, const float* __restrict__ maskg,
            __half* __restrict__ Ctx)
{
    extern __shared__ char sm_raw[];
    __half* Qs  = (__half*)sm_raw;            // [128][72]
    __half* Ks  = Qs + 128 * 72;              // [4][64][72]
    __half* Vs  = Ks + 4 * KV_ST;             // [4][64][72]
    float*  Msk = (float*)(Vs + 4 * KV_ST);   // [4][64]

    const int tid  = threadIdx.x;
    const int lane = tid & 31;
    const int w    = tid >> 5;
    const int g    = lane >> 2;
    const int t    = lane & 3;
    const int qtile = blockIdx.x, h = blockIdx.y, b = blockIdx.z;
    const int tok0 = b * SS + qtile * 128;

    {
        int r = tid >> 1;
        const __half* src = Qg + (size_t)(tok0 + r) * HH + h * HDD;
        uint32_t dst = smem_u32(Qs + r * 72);
        int cb = (tid & 1) * 4;
#pragma unroll
        for (int j = 0; j < 4; j++) CP_ASYNC(dst + (cb + j) * 16, src + (cb + j) * 8);
    }

    auto load_tile = [&](int kt, int st) {
        int r = tid >> 2;
        int cb = (tid & 3) * 2;
        const __half* ks = Kg + (size_t)(b * SS + kt * 64 + r) * HH + h * HDD;
        const __half* vs = Vg + (size_t)(b * SS + kt * 64 + r) * HH + h * HDD;
        uint32_t kd = smem_u32(Ks + st * KV_ST + r * 72);
        uint32_t vd = smem_u32(Vs + st * KV_ST + r * 72);
#pragma unroll
        for (int j = 0; j < 2; j++) {
            CP_ASYNC(kd + (cb + j) * 16, ks + (cb + j) * 8);
            CP_ASYNC(vd + (cb + j) * 16, vs + (cb + j) * 8);
        }
        if (tid < 16)
            CP_ASYNC(smem_u32(Msk + st * 64 + tid * 4), maskg + (size_t)b * SS + kt * 64 + tid * 4);
    };

    load_tile(0, 0); CP_COMMIT();
    load_tile(1, 1); CP_COMMIT();
    load_tile(2, 2); CP_COMMIT();
    CP_WAIT2();
    __syncthreads();

    uint32_t qa[4][4];
    {
        uint32_t base = smem_u32(Qs + (16 * w + (lane & 15)) * 72 + (lane >> 4) * 8);
#pragma unroll
        for (int ks = 0; ks < 4; ks++) ldsm4(qa[ks], base + ks * 32);
    }

    float o[8][4];
#pragma unroll
    for (int nt = 0; nt < 8; nt++)
#pragma unroll
        for (int i = 0; i < 4; i++) o[nt][i] = 0.0f;
    float lacc[4] = {0.0f, 0.0f, 0.0f, 0.0f};
    const float SC2 = 0.125f * LOG2E;
    const uint32_t ONESH2 = 0x3C003C00u;
    const uint32_t onesb[2] = { ONESH2, ONESH2 };

    const uint32_t kfrag = smem_u32(Ks) + (lane & 7) * 144 + (lane >> 3) * 16;
    const uint32_t vfrag = smem_u32(Vs) + lane * 144;

    const int NKV = SS / 64;
    for (int kt = 0; kt < NKV; kt += 4) {
#pragma unroll
        for (int j = 0; j < 4; j++) {
            if (kt + j + 3 < NKV)      { load_tile(kt + j + 3, (j + 3) & 3); CP_COMMIT(); CP_WAIT3(); }
            else if (kt + j + 2 < NKV) { CP_WAIT2(); }
            else if (kt + j + 1 < NKV) { CP_WAIT1(); }
            else                       { CP_WAIT0(); }

            float s[8][4];
            const uint32_t kb0 = kfrag + j * KV_ST_B;
#pragma unroll
            for (int nt = 0; nt < 8; nt++) {
#pragma unroll
                for (int i = 0; i < 4; i++) s[nt][i] = 0.0f;
                uint32_t bb[8];
                ldsm4(&bb[0], kb0 + nt * (8 * 144));
                ldsm4(&bb[4], kb0 + nt * (8 * 144) + 64);
#pragma unroll
                for (int ks = 0; ks < 4; ks++) mma16816(s[nt], qa[ks], &bb[2 * ks]);
            }

            const float* mp = Msk + j * 64;
            uint32_t pk[8][2];
#pragma unroll
            for (int nt = 0; nt < 8; nt++) {
                float2 mk = *(const float2*)(mp + 8 * nt + 2 * t);
                float mkx = mk.x * LOG2E, mky = mk.y * LOG2E;
                float x0 = fmaf(s[nt][0], SC2, mkx);
                float x1 = fmaf(s[nt][1], SC2, mky);
                float x2 = fmaf(s[nt][2], SC2, mkx);
                float x3 = fmaf(s[nt][3], SC2, mky);
                pk[nt][0] = h2_as_u32(h2exp2(__floats2half2_rn(x0, x1)));
                pk[nt][1] = h2_as_u32(h2exp2(__floats2half2_rn(x2, x3)));
            }

            const uint32_t vb0 = vfrag + j * KV_ST_B;
#pragma unroll
            for (int nt = 0; nt < 8; nt++) {
                uint32_t vb[8];
                ldsm4t(&vb[0], vb0 + nt * 16);
                ldsm4t(&vb[4], vb0 + nt * 16 + 32 * 144);
#pragma unroll
                for (int kb = 0; kb < 4; kb++) {
                    uint32_t pa[4] = { pk[2*kb][0], pk[2*kb][1], pk[2*kb+1][0], pk[2*kb+1][1] };
                    mma16816(o[nt], pa, &vb[2 * kb]);
                }
            }
#pragma unroll
            for (int kb = 0; kb < 4; kb++) {
                uint32_t pa[4] = { pk[2*kb][0], pk[2*kb][1], pk[2*kb+1][0], pk[2*kb+1][1] };
                mma16816(lacc, pa, onesb);
            }
            __syncthreads();
        }
    }

    float ilo = 1.0f / lacc[0], ihi = 1.0f / lacc[2];
    int row = tok0 + 16 * w + g;
    __half* cb0 = Ctx + (size_t)row * HH + h * HDD + 2 * t;
    __half* cb1 = cb0 + (size_t)8 * HH;
#pragma unroll
    for (int nt = 0; nt < 8; nt++) {
        *(__half2*)(cb0 + 8 * nt) = __floats2half2_rn(o[nt][0] * ilo, o[nt][1] * ilo);
        *(__half2*)(cb1 + 8 * nt) = __floats2half2_rn(o[nt][2] * ihi, o[nt][3] * ihi);
    }
}

// ---------------------------------------------------------------------------
// LayerNorm(hidden) * gamma + beta + query
// ---------------------------------------------------------------------------
__global__ __launch_bounds__(256)
void ln_residual_kernel(const float* __restrict__ Hd, const float* __restrict__ X,
                        const float* __restrict__ gamma, const float* __restrict__ beta,
                        float* __restrict__ out)
{
    const int row = blockIdx.x;
    const int tid = threadIdx.x;
    const size_t base = (size_t)row * HH;

    float4 hv = ((const float4*)(Hd + base))[tid];
    float s  = hv.x + hv.y + hv.z + hv.w;
    float sq = hv.x * hv.x + hv.y * hv.y + hv.z * hv.z + hv.w * hv.w;
#pragma unroll
    for (int off = 16; off > 0; off >>= 1) {
        s  += __shfl_down_sync(0xffffffffu, s,  off);
        sq += __shfl_down_sync(0xffffffffu, sq, off);
    }
    __shared__ float ws[8], wsq[8], stats[2];
    int wid = tid >> 5, lane = tid & 31;
    if (lane == 0) { ws[wid] = s; wsq[wid] = sq; }
    __syncthreads();
    if (tid == 0) {
        float S = 0.0f, SQ = 0.0f;
#pragma unroll
        for (int i = 0; i < 8; i++) { S += ws[i]; SQ += wsq[i]; }
        float mean = S * (1.0f / HH);
        float var  = SQ * (1.0f / HH) - mean * mean;
        stats[0] = mean;
        stats[1] = rsqrtf(var + 1e-12f);
    }
    __syncthreads();
    float mean = stats[0], rstd = stats[1];

    float4 gv = ((const float4*)gamma)[tid];
    float4 bv = ((const float4*)beta)[tid];
    float4 xv = ((const float4*)(X + base))[tid];
    float4 ov;
    ov.x = (hv.x - mean) * rstd * gv.x + bv.x + xv.x;
    ov.y = (hv.y - mean) * rstd * gv.y + bv.y + xv.y;
    ov.z = (hv.z - mean) * rstd * gv.z + bv.z + xv.z;
    ov.w = (hv.w - mean) * rstd * gv.w + bv.w + xv.w;
    ((float4*)(out + base))[tid] = ov;
}

// ---------------------------------------------------------------------------
extern "C" void kernel_launch(void* const* d_in, const int* in_sizes, int n_in,
                              void* d_out, int out_size)
{
    const float* query = (const float*)d_in[0];
    const float* mask  = (const float*)d_in[1];
    const float* Wq    = (const float*)d_in[2];
    const float* bq    = (const float*)d_in[3];
    const float* Wk    = (const float*)d_in[4];
    const float* bk    = (const float*)d_in[5];
    const float* Wv    = (const float*)d_in[6];
    const float* bv    = (const float*)d_in[7];
    const float* Wd    = (const float*)d_in[8];
    const float* bd    = (const float*)d_in[9];
    const float* gamma = (const float*)d_in[10];
    const float* beta  = (const float*)d_in[11];
    float* out = (float*)d_out;

    __half *Xh, *Wh, *Qh, *Kh, *Vh, *Ch;
    float* Hp;
    cudaGetSymbolAddress((void**)&Xh,  g_Xh);
    cudaGetSymbolAddress((void**)&Wh,  g_Wh);
    cudaGetSymbolAddress((void**)&Qh,  g_Qh);
    cudaGetSymbolAddress((void**)&Kh,  g_Kh);
    cudaGetSymbolAddress((void**)&Vh,  g_Vh);
    cudaGetSymbolAddress((void**)&Ch,  g_Ch);
    cudaGetSymbolAddress((void**)&Hp,  g_Hd);

    __half* Wqh = Wh + 0 * (size_t)HH * HH;
    __half* Wkh = Wh + 1 * (size_t)HH * HH;
    __half* Wvh = Wh + 2 * (size_t)HH * HH;
    __half* Wdh = Wh + 3 * (size_t)HH * HH;

    // fp32 -> fp16 prep
    f2h_kernel<<<TOT / 4 / 256, 256>>>((const float4*)query, (__half2*)Xh, TOT / 4);
    f2h_w_kernel<<<dim3(HH * HH / 4 / 256, 4), 256>>>(
        (const float4*)Wq, (const float4*)Wk, (const float4*)Wv, (const float4*)Wd, (__half2*)Wh);

    // fused QKV projection: A tile shared across 3 weights
    const int qsmem = (4 * A_STQ + 12 * B_STQ) * 2;   // 145,408 B
    cudaFuncSetAttribute(gemm_qkv, cudaFuncAttributeMaxDynamicSharedMemorySize, qsmem);
    dim3 gq(HH / 128, ROWS / 128);   // (8, 64)
    gemm_qkv<<<gq, 512, qsmem>>>(Xh, Wqh, Wkh, Wvh, bq, bk, bv, Qh, Kh, Vh);

    // attention (proven kernel)
    const size_t asmem = (size_t)(128 * 72 + 8 * KV_ST) * sizeof(__half) + 4 * 64 * sizeof(float);
    cudaFuncSetAttribute(attn16, cudaFuncAttributeMaxDynamicSharedMemorySize, (int)asmem);
    attn16<<<dim3(SS / 128, NHH, BB), 256, asmem>>>(Qh, Kh, Vh, mask, Ch);

    // output projection (proven kernel, float out)
    const int gsmem = (4 * A_ST + 4 * B_ST) * 2;   // 75,776 B
    cudaFuncSetAttribute(gemm16, cudaFuncAttributeMaxDynamicSharedMemorySize, gsmem);
    dim3 gg(HH / 128, ROWS / 128);
    gemm16<<<gg, 256, gsmem>>>(Ch, Wdh, bd, Hp);

    // LN + residual
    ln_residual_kernel<<<ROWS, 256>>>(Hp, query, gamma, beta, out);
}